// round 9
// baseline (speedup 1.0000x reference)
#include <cuda_runtime.h>
#include <cuda_fp16.h>
#include <mma.h>
#include <cstdint>

using namespace nvcuda;

// Problem dims (fixed by setup_inputs)
constexpr int U = 128, I = 256, J = 512, C = 128, E = 128;

// ---------------- scratch (device globals) ----------------------------------
__device__ float  g_skb[U * J];            // inter . w2 + b
__device__ float  g_upart[U * C];          // user @ W1 + b_mlp
__device__ int    g_pa[32], g_pb[32];      // mask-sniff partial flags
__device__ __half g_Zh[U * J * C];         // Z = interacted @ W2, fp16
// dependency flags (self-resetting each launch; zero-init at load)
__device__ int    g_zflag[U];              // 9 arrivals: 8 Z-blocks + upart
__device__ int    g_mdone;                 // 32 sniff arrivals
__device__ int    g_done[U];               // gemm consumers per user (4)
__device__ int    g_gdone;                 // total gemm blocks (512)

// ---------------- low-level helpers ------------------------------------------
__device__ __forceinline__ void cp_async16(void* smem, const void* gmem)
{
    unsigned s = (unsigned)__cvta_generic_to_shared(smem);
    asm volatile("cp.async.cg.shared.global [%0], [%1], 16;" :: "r"(s), "l"(gmem));
}
__device__ __forceinline__ void cp_commit()
{
    asm volatile("cp.async.commit_group;" ::: "memory");
}
template<int N>
__device__ __forceinline__ void cp_wait()
{
    asm volatile("cp.async.wait_group %0;" :: "n"(N) : "memory");
}
__device__ __forceinline__ int ld_acquire(const int* p)
{
    int v;
    asm volatile("ld.acquire.gpu.global.s32 %0, [%1];" : "=r"(v) : "l"(p));
    return v;
}

// ---------------- MMA micro-tile (BM=64, BN=128, BK=64, 8 warps) -----------
template<int LDA, int LDB>
__device__ __forceinline__ void mma_tile64(
    const __half* A, const __half* B, int wm, int wn,
    wmma::fragment<wmma::accumulator, 16, 16, 16, float> (&acc)[2][2])
{
    #pragma unroll
    for (int kk = 0; kk < 64; kk += 16) {
        wmma::fragment<wmma::matrix_a, 16, 16, 16, __half, wmma::row_major> a[2];
        wmma::fragment<wmma::matrix_b, 16, 16, 16, __half, wmma::row_major> b[2];
        wmma::load_matrix_sync(a[0], A + (wm * 32) * LDA + kk, LDA);
        wmma::load_matrix_sync(a[1], A + (wm * 32 + 16) * LDA + kk, LDA);
        wmma::load_matrix_sync(b[0], B + kk * LDB + wn * 32, LDB);
        wmma::load_matrix_sync(b[1], B + kk * LDB + wn * 32 + 16, LDB);
        #pragma unroll
        for (int fi = 0; fi < 2; fi++)
            #pragma unroll
            for (int fj = 0; fj < 2; fj++)
                wmma::mma_sync(acc[fi][fj], a[fi], b[fj], acc[fi][fj]);
    }
}

// ---------------- smem layout constants --------------------------------------
constexpr int BM   = 64;
constexpr int LDW  = 520;                         // wsm half stride (bank-free)
constexpr int BOFF = BM * LDW * 2;                // 66,560
constexpr int BS_STAGE = 64 * 136;                // halves per stage
constexpr int SOFF = BOFF + 2 * BS_STAGE * 2;     // 101,376
constexpr int SMEM_MAIN = SOFF + (64 + 64 + 512 + 512) * 4;  // 105,984

// ======================= role bodies =========================================

__device__ void role_sniff(char* sm, int u, const unsigned* __restrict__ mask)
{
    const int tid = threadIdx.x, lane = tid & 31;
    int a = 0, b = 0;
    #pragma unroll
    for (int r = 0; r < 2; r++) {
        unsigned w = mask[u * 512 + tid + 256 * r];
        a |= (w != 0u && w != 1u);
        b |= (w != 0u && w != 0x3F800000u);
    }
    int* s_f = (int*)sm;
    if (tid == 0) { s_f[0] = 0; s_f[1] = 0; }
    __syncthreads();
    a = __reduce_or_sync(0xffffffffu, a);
    b = __reduce_or_sync(0xffffffffu, b);
    if (lane == 0) { atomicOr(&s_f[0], a); atomicOr(&s_f[1], b); }
    __syncthreads();
    if (tid == 0) {
        g_pa[u] = s_f[0];
        g_pb[u] = s_f[1];
        __threadfence();
        atomicAdd(&g_mdone, 1);
    }
}

__device__ void role_upart(char* sm, int u, const float* __restrict__ user,
                           const float* __restrict__ Wmlp,
                           const float* __restrict__ bmlp)
{
    const int tid = threadIdx.x;
    float* usm  = (float*)sm;          // 128 floats
    float* psum = usm + 128;           // 256 floats
    if (tid < 128) usm[tid] = user[u * E + tid];
    __syncthreads();
    int c = tid & 127, h = tid >> 7;
    float acc0 = 0.f, acc1 = 0.f;
    int e0 = h * 64;
    #pragma unroll 16
    for (int e = 0; e < 64; e += 2) {
        acc0 += usm[e0 + e]     * __ldg(Wmlp + (e0 + e) * C + c);
        acc1 += usm[e0 + e + 1] * __ldg(Wmlp + (e0 + e + 1) * C + c);
    }
    psum[tid] = acc0 + acc1;
    __syncthreads();
    if (tid < 128)
        g_upart[u * C + tid] = psum[tid] + psum[tid + 128] + __ldg(bmlp + tid);
    __syncthreads();
    __threadfence();
    if (tid == 0) atomicAdd(&g_zflag[u], 1);
}

__device__ void role_zblock(char* sm, int u, int j0,
                            const float* __restrict__ inter,
                            const float* __restrict__ w2,
                            const float* __restrict__ bd,
                            const float* __restrict__ Wmlp)
{
    __half* As = (__half*)sm;                    // 64 x 128 (lda 136)
    __half* Bs = (__half*)(sm + 64 * 136 * 2);
    float*  Cs = (float*)sm;                     // epilogue staging
    const int tid = threadIdx.x, wid = tid >> 5, lane = tid & 31;
    const int wm = wid >> 2, wn = wid & 3;

    const float4 wv = __ldg((const float4*)w2 + lane);
    const float bias = __ldg(bd);

    // batched loads (MLP=8), then convert + store + dot
    float4 v[8];
    #pragma unroll
    for (int r = 0; r < 8; r++)
        v[r] = *(const float4*)(inter + ((size_t)(u * J + j0 + wid + 8 * r)) * C + lane * 4);
    #pragma unroll
    for (int r = 0; r < 8; r++) {
        int row = wid + 8 * r;
        __half2 h01 = __floats2half2_rn(v[r].x, v[r].y);
        __half2 h23 = __floats2half2_rn(v[r].z, v[r].w);
        uint2 pk; pk.x = *(unsigned*)&h01; pk.y = *(unsigned*)&h23;
        *(uint2*)(As + row * 136 + lane * 4) = pk;
        float d = v[r].x * wv.x + v[r].y * wv.y + v[r].z * wv.z + v[r].w * wv.w;
        #pragma unroll
        for (int off = 16; off; off >>= 1) d += __shfl_xor_sync(0xffffffffu, d, off);
        if (lane == 0) g_skb[u * J + j0 + row] = d + bias;
    }
    __syncthreads();

    wmma::fragment<wmma::accumulator, 16, 16, 16, float> acc[2][2];
    #pragma unroll
    for (int fi = 0; fi < 2; fi++)
        for (int fj = 0; fj < 2; fj++) wmma::fill_fragment(acc[fi][fj], 0.f);

    for (int k0 = 0; k0 < C; k0 += 64) {
        // Bs <- W_mlp[E+k0 .. E+k0+63, :] fp32->fp16 (L2-hot)
        #pragma unroll
        for (int r = 0; r < 8; r++) {
            int idx = tid + 256 * r;
            int br = idx >> 5, bc = (idx & 31) * 4;
            float4 t = __ldg((const float4*)(Wmlp + (size_t)(E + k0 + br) * C + bc));
            __half2 h01 = __floats2half2_rn(t.x, t.y);
            __half2 h23 = __floats2half2_rn(t.z, t.w);
            uint2 pk; pk.x = *(unsigned*)&h01; pk.y = *(unsigned*)&h23;
            *(uint2*)(Bs + br * 136 + bc) = pk;
        }
        __syncthreads();
        mma_tile64<136, 136>(As + k0, Bs, wm, wn, acc);
        __syncthreads();
    }

    #pragma unroll
    for (int fi = 0; fi < 2; fi++)
        for (int fj = 0; fj < 2; fj++)
            wmma::store_matrix_sync(
                Cs + (wm * 32 + fi * 16) * 128 + wn * 32 + fj * 16,
                acc[fi][fj], 128, wmma::mem_row_major);
    __syncthreads();
    #pragma unroll
    for (int it = 0; it < 8; it++) {
        int idx = tid + 256 * it, row = idx >> 5, c4 = (idx & 31) * 4;
        float4 t = *(const float4*)(Cs + row * 128 + c4);
        __half2 h01 = __floats2half2_rn(t.x, t.y);
        __half2 h23 = __floats2half2_rn(t.z, t.w);
        uint2 pk; pk.x = *(unsigned*)&h01; pk.y = *(unsigned*)&h23;
        *(uint2*)(g_Zh + ((size_t)(u * J + j0 + row)) * C + c4) = pk;
    }
    __syncthreads();
    __threadfence();
    if (tid == 0) atomicAdd(&g_zflag[u], 1);
}

__device__ void role_gemm(char* dsm, int u, int m0,
                          const float* __restrict__ target,
                          const float* __restrict__ w1,
                          const void* __restrict__ mask,
                          float* __restrict__ out_ctx,
                          float* __restrict__ out_attn)
{
    __half* wsm   = (__half*)dsm;            // 64 x 512 (ld 520)
    __half* Bs    = (__half*)(dsm + BOFF);   // [2][64*136]
    float*  Cs    = (float*)dsm;             // union over wsm (epilogue)
    float* st_sm  = (float*)(dsm + SOFF);
    float* inv_sm = st_sm + 64;
    float* skb_sm = inv_sm + 64;
    float* m_sm   = skb_sm + 512;

    const int tid = threadIdx.x, wid = tid >> 5, lane = tid & 31;
    const int wm = wid >> 2, wn = wid & 3;
    const float L2E = 1.4426950408889634f;

    // phase 0a: target dots (independent of producers) — batched loads MLP=8
    {
        float4 tv[8];
        #pragma unroll
        for (int r = 0; r < 8; r++)
            tv[r] = *(const float4*)(target + ((size_t)(u * I + m0 + wid + 8 * r)) * C + lane * 4);
        float4 wv = __ldg((const float4*)w1 + lane);
        #pragma unroll
        for (int r = 0; r < 8; r++) {
            float d = tv[r].x * wv.x + tv[r].y * wv.y + tv[r].z * wv.z + tv[r].w * wv.w;
            #pragma unroll
            for (int off = 16; off; off >>= 1) d += __shfl_xor_sync(0xffffffffu, d, off);
            if (lane == 0) st_sm[wid + 8 * r] = d;
        }
    }

    // spin until producers done (thread 0; acquire + backoff)
    if (tid == 0) {
        while (ld_acquire(&g_mdone) < 32) __nanosleep(64);
        while (ld_acquire(&g_zflag[u]) < 9) __nanosleep(64);
    }
    __syncthreads();

    // mask mode
    int fa = g_pa[lane], fb = g_pb[lane];
    fa = __reduce_or_sync(0xffffffffu, fa);
    fb = __reduce_or_sync(0xffffffffu, fb);
    const int mode = !fa ? 1 : (!fb ? 2 : 0);

    // phase 0b: skb + mask -> smem; prefetch Zh tile 0
    #pragma unroll
    for (int r = 0; r < 2; r++) {
        int k = tid + 256 * r;
        skb_sm[k] = g_skb[u * J + k];
        float mv;
        if (mode == 1)      mv = ((const int*)mask)[u * J + k] ? 1.f : 0.f;
        else if (mode == 2) mv = ((const float*)mask)[u * J + k];
        else                mv = ((const unsigned char*)mask)[u * J + k] ? 1.f : 0.f;
        m_sm[k] = mv;
    }
    #pragma unroll
    for (int r = 0; r < 4; r++) {
        int idx = tid + 256 * r, br = idx >> 4, bc = (idx & 15) * 8;
        cp_async16(Bs + br * 136 + bc, g_Zh + ((size_t)u * J + br) * C + bc);
    }
    cp_commit();
    __syncthreads();

    // phase 1: softmax numerators -> wsm fp16; row sums
    {
        int row = tid >> 2, sub = tid & 3;
        float stv = st_sm[row];
        float sum = 0.f;
        #pragma unroll
        for (int k = 0; k < 64; k++) {
            int c = sub * 2 + 8 * k;
            float x0 = stv + skb_sm[c], x1 = stv + skb_sm[c + 1];
            float t0, t1, e0, e1;
            asm("tanh.approx.f32 %0,%1;" : "=f"(t0) : "f"(x0));
            asm("tanh.approx.f32 %0,%1;" : "=f"(t1) : "f"(x1));
            asm("ex2.approx.f32 %0,%1;"  : "=f"(e0) : "f"(t0 * L2E));
            asm("ex2.approx.f32 %0,%1;"  : "=f"(e1) : "f"(t1 * L2E));
            e0 *= m_sm[c]; e1 *= m_sm[c + 1];
            *(__half2*)(wsm + row * LDW + c) = __floats2half2_rn(e0, e1);
            sum += e0 + e1;
        }
        sum += __shfl_xor_sync(0xffffffffu, sum, 1);
        sum += __shfl_xor_sync(0xffffffffu, sum, 2);
        if (sub == 0) inv_sm[row] = __fdividef(1.f, sum);
    }
    __syncthreads();

    // phase 2: MMA over J, double-buffered cp.async Bs
    wmma::fragment<wmma::accumulator, 16, 16, 16, float> acc[2][2];
    #pragma unroll
    for (int fi = 0; fi < 2; fi++)
        for (int fj = 0; fj < 2; fj++) wmma::fill_fragment(acc[fi][fj], 0.f);

    for (int kt = 0; kt < 8; kt++) {
        if (kt < 7) {
            __half* dst = Bs + ((kt + 1) & 1) * BS_STAGE;
            #pragma unroll
            for (int r = 0; r < 4; r++) {
                int idx = tid + 256 * r, br = idx >> 4, bc = (idx & 15) * 8;
                cp_async16(dst + br * 136 + bc,
                           g_Zh + ((size_t)u * J + (kt + 1) * 64 + br) * C + bc);
            }
            cp_commit();
            cp_wait<1>();
        } else {
            cp_wait<0>();
        }
        __syncthreads();
        mma_tile64<LDW, 136>(wsm + kt * 64, Bs + (kt & 1) * BS_STAGE, wm, wn, acc);
        __syncthreads();
    }

    // phase 3: normalized attn -> gmem
    {
        float* ab = out_attn + ((size_t)(u * I + m0)) * J;
        #pragma unroll
        for (int it = 0; it < 32; it++) {
            int idx = tid + 256 * it;
            int row = idx >> 7, c4 = (idx & 127) * 4;
            uint2 pk = *(uint2*)(wsm + row * LDW + c4);
            __half2 h01 = *(__half2*)&pk.x, h23 = *(__half2*)&pk.y;
            float iv = inv_sm[row];
            float2 f01 = __half22float2(h01), f23 = __half22float2(h23);
            *(float4*)(ab + row * J + c4) =
                make_float4(f01.x * iv, f01.y * iv, f23.x * iv, f23.y * iv);
        }
    }
    __syncthreads();   // wsm reads done; Cs may alias it

    // epilogue: relu(acc*inv + upart) -> out_ctx
    #pragma unroll
    for (int fi = 0; fi < 2; fi++)
        for (int fj = 0; fj < 2; fj++)
            wmma::store_matrix_sync(
                Cs + (wm * 32 + fi * 16) * 128 + wn * 32 + fj * 16,
                acc[fi][fj], 128, wmma::mem_row_major);
    __syncthreads();
    {
        const float4* up4 = (const float4*)(g_upart + u * C);
        float* ob = out_ctx + ((size_t)(u * I + m0)) * C;
        #pragma unroll
        for (int it = 0; it < 8; it++) {
            int idx = tid + 256 * it, row = idx >> 5, c4 = idx & 31;
            float4 t = ((const float4*)Cs)[idx];
            float iv = inv_sm[row];
            float4 up = __ldg(up4 + c4);
            t.x = fmaxf(fmaf(t.x, iv, up.x), 0.f);
            t.y = fmaxf(fmaf(t.y, iv, up.y), 0.f);
            t.z = fmaxf(fmaf(t.z, iv, up.z), 0.f);
            t.w = fmaxf(fmaf(t.w, iv, up.w), 0.f);
            ((float4*)ob)[idx] = t;
        }
    }

    // self-reset flags (deterministic across graph replays)
    __threadfence();
    if (tid == 0) {
        int d = atomicAdd(&g_done[u], 1);
        if (d == 3) { atomicExch(&g_zflag[u], 0); atomicExch(&g_done[u], 0); }
        int t = atomicAdd(&g_gdone, 1);
        if (t == (U * (I / BM)) - 1) { atomicExch(&g_mdone, 0); atomicExch(&g_gdone, 0); }
    }
}

// ======================= mega kernel =========================================
// 1D grid, dispatch (= bid) order:
//   [0,32)        sniff
//   [32,160)      upart (u = bid-32)
//   [160,1744)    groups of 12: g = (bid-160)/12, r = (bid-160)%12
//                   r<8 : Z-block (u=g, j0=r*64)        [skip if g>=128]
//                   r>=8: gemm    (u=g-4, m0=(r-8)*64)  [skip if g<4]
__global__ __launch_bounds__(256, 2) void mega_kernel(
    const float* __restrict__ target, const float* __restrict__ inter,
    const float* __restrict__ user,   const void*  __restrict__ mask,
    const float* __restrict__ wdense, const float* __restrict__ bdense,
    const float* __restrict__ Wmlp,   const float* __restrict__ bmlp,
    float* __restrict__ out_ctx, float* __restrict__ out_attn)
{
    extern __shared__ __align__(16) char dsm[];
    const int bid = blockIdx.x;

    if (bid < 32) {
        role_sniff(dsm, bid, (const unsigned*)mask);
        return;
    }
    if (bid < 160) {
        role_upart(dsm, bid - 32, user, Wmlp, bmlp);
        return;
    }
    int idx = bid - 160;
    int g = idx / 12, r = idx - g * 12;
    if (r < 8) {
        if (g < U)
            role_zblock(dsm, g, r * 64, inter, wdense + C, bdense, Wmlp);
    } else {
        if (g >= 4)
            role_gemm(dsm, g - 4, (r - 8) * 64, target, wdense, mask,
                      out_ctx, out_attn);
    }
}

// ---------------- launcher ---------------------------------------------------
extern "C" void kernel_launch(void* const* d_in, const int* in_sizes, int n_in,
                              void* d_out, int out_size)
{
    const float* target = (const float*)d_in[0];  // (U,I,C)
    const float* inter  = (const float*)d_in[1];  // (U,J,C)
    const float* user   = (const float*)d_in[2];  // (U,E)
    const void*  mask   = d_in[3];                // (U,J) dtype sniffed
    const float* wdense = (const float*)d_in[4];  // (2C,)
    const float* bdense = (const float*)d_in[5];  // (1,)
    const float* Wmlp   = (const float*)d_in[6];  // (E+C, C)
    const float* bmlp   = (const float*)d_in[7];  // (C,)

    float* out_ctx  = (float*)d_out;                       // (U,I,C)
    float* out_attn = (float*)d_out + (size_t)U * I * C;   // (U,I,J)

    cudaFuncSetAttribute(mega_kernel,
                         cudaFuncAttributeMaxDynamicSharedMemorySize, SMEM_MAIN);

    const int nblocks = 160 + 132 * 12;   // 1744
    mega_kernel<<<nblocks, 256, SMEM_MAIN>>>(target, inter, user, mask,
                                             wdense, bdense, Wmlp, bmlp,
                                             out_ctx, out_attn);
}

// round 10
// speedup vs baseline: 1.2680x; 1.2680x over previous
#include <cuda_runtime.h>
#include <cuda_fp16.h>
#include <mma.h>
#include <cstdint>

using namespace nvcuda;

// Problem dims (fixed by setup_inputs)
constexpr int U = 128, I = 256, J = 512, C = 128, E = 128;

// ---------------- scratch (device globals) ----------------------------------
__device__ float  g_skb[U * J];            // inter . w2 + b
__device__ float  g_st[U * I];             // target . w1
__device__ float  g_upart[U * C];          // user @ W1 + b_mlp
__device__ int    g_pa[32], g_pb[32];      // mask-sniff partial flags
__device__ __half g_Zh[U * J * C];         // Z = interacted @ W2, fp16

// ---------------- cp.async helpers ------------------------------------------
__device__ __forceinline__ void cp_async16(void* smem, const void* gmem)
{
    unsigned s = (unsigned)__cvta_generic_to_shared(smem);
    asm volatile("cp.async.cg.shared.global [%0], [%1], 16;" :: "r"(s), "l"(gmem));
}
__device__ __forceinline__ void cp_commit()
{
    asm volatile("cp.async.commit_group;" ::: "memory");
}
template<int N>
__device__ __forceinline__ void cp_wait()
{
    asm volatile("cp.async.wait_group %0;" :: "n"(N) : "memory");
}

// ---------------- MMA micro-tiles -------------------------------------------
template<int LDA, int LDB>
__device__ __forceinline__ void mma_tile64(
    const __half* A, const __half* B, int wm, int wn,
    wmma::fragment<wmma::accumulator, 16, 16, 16, float> (&acc)[2][2])
{
    #pragma unroll
    for (int kk = 0; kk < 64; kk += 16) {
        wmma::fragment<wmma::matrix_a, 16, 16, 16, __half, wmma::row_major> a[2];
        wmma::fragment<wmma::matrix_b, 16, 16, 16, __half, wmma::row_major> b[2];
        wmma::load_matrix_sync(a[0], A + (wm * 32) * LDA + kk, LDA);
        wmma::load_matrix_sync(a[1], A + (wm * 32 + 16) * LDA + kk, LDA);
        wmma::load_matrix_sync(b[0], B + kk * LDB + wn * 32, LDB);
        wmma::load_matrix_sync(b[1], B + kk * LDB + wn * 32 + 16, LDB);
        #pragma unroll
        for (int fi = 0; fi < 2; fi++)
            #pragma unroll
            for (int fj = 0; fj < 2; fj++)
                wmma::mma_sync(acc[fi][fj], a[fi], b[fj], acc[fi][fj]);
    }
}

template<int LDA, int LDB>
__device__ __forceinline__ void mma_tile128(
    const __half* A, const __half* B, int wm, int wn,
    wmma::fragment<wmma::accumulator, 16, 16, 16, float> (&acc)[4][2])
{
    #pragma unroll
    for (int kk = 0; kk < 64; kk += 16) {
        wmma::fragment<wmma::matrix_a, 16, 16, 16, __half, wmma::row_major> a[4];
        wmma::fragment<wmma::matrix_b, 16, 16, 16, __half, wmma::row_major> b[2];
        #pragma unroll
        for (int fi = 0; fi < 4; fi++)
            wmma::load_matrix_sync(a[fi], A + (wm * 64 + fi * 16) * LDA + kk, LDA);
        #pragma unroll
        for (int fj = 0; fj < 2; fj++)
            wmma::load_matrix_sync(b[fj], B + kk * LDB + wn * 32 + fj * 16, LDB);
        #pragma unroll
        for (int fi = 0; fi < 4; fi++)
            #pragma unroll
            for (int fj = 0; fj < 2; fj++)
                wmma::mma_sync(acc[fi][fj], a[fi], b[fj], acc[fi][fj]);
    }
}

// ---------------- fusedZ: inter -> skb + Zh; st, upart, sniff ride along ---
// grid (14, U), 256 thr.
//   x<8          : 64 j-rows of user u (GEMM Z)
//   x==8         : upart for u
//   x in [9,13)  : st block, rows (x-9)*64 .. +63 of user u
//   x==13 && u<32: mask sniff partial
__global__ __launch_bounds__(256, 2) void fusedz_kernel(
    const float* __restrict__ inter, const float* __restrict__ wdense,
    const float* __restrict__ bd, const float* __restrict__ user,
    const float* __restrict__ Wmlp, const float* __restrict__ bmlp,
    const float* __restrict__ target, const unsigned* __restrict__ mask)
{
    __shared__ __align__(16) char sm[64 * 136 * 2 * 2];  // 34,816 B
    const int u = blockIdx.y;
    const int tid = threadIdx.x, wid = tid >> 5, lane = tid & 31;

    if (blockIdx.x == 13) {
        // ---- mask sniff partial ----
        if (u >= 32) return;
        int a = 0, b = 0;
        #pragma unroll
        for (int r = 0; r < 2; r++) {
            unsigned w = mask[u * 512 + tid + 256 * r];
            a |= (w != 0u && w != 1u);
            b |= (w != 0u && w != 0x3F800000u);
        }
        int* s_f = (int*)sm;
        if (tid == 0) { s_f[0] = 0; s_f[1] = 0; }
        __syncthreads();
        a = __reduce_or_sync(0xffffffffu, a);
        b = __reduce_or_sync(0xffffffffu, b);
        if (lane == 0) { atomicOr(&s_f[0], a); atomicOr(&s_f[1], b); }
        __syncthreads();
        if (tid == 0) { g_pa[u] = s_f[0]; g_pb[u] = s_f[1]; }
        return;
    }

    if (blockIdx.x >= 9) {
        // ---- st block: 64 rows of target dots (batched loads) ----
        const int m0 = (blockIdx.x - 9) * 64;
        float4 tv[8];
        #pragma unroll
        for (int r = 0; r < 8; r++)
            tv[r] = *(const float4*)(target + ((size_t)(u * I + m0 + wid + 8 * r)) * C + lane * 4);
        float4 wv = __ldg((const float4*)wdense + lane);
        #pragma unroll
        for (int r = 0; r < 8; r++) {
            float d = tv[r].x * wv.x + tv[r].y * wv.y + tv[r].z * wv.z + tv[r].w * wv.w;
            #pragma unroll
            for (int off = 16; off; off >>= 1) d += __shfl_xor_sync(0xffffffffu, d, off);
            if (lane == 0) g_st[u * I + m0 + wid + 8 * r] = d;
        }
        return;
    }

    if (blockIdx.x == 8) {
        // ---- upart: g_upart[u] = user[u] @ Wmlp[:E] + bmlp ----
        float* usm  = (float*)sm;          // 128 floats
        float* psum = usm + 128;           // 256 floats
        if (tid < 128) usm[tid] = user[u * E + tid];
        __syncthreads();
        int c = tid & 127, h = tid >> 7;
        float acc0 = 0.f, acc1 = 0.f;
        int e0 = h * 64;
        #pragma unroll 16
        for (int e = 0; e < 64; e += 2) {
            acc0 += usm[e0 + e]     * __ldg(Wmlp + (e0 + e) * C + c);
            acc1 += usm[e0 + e + 1] * __ldg(Wmlp + (e0 + e + 1) * C + c);
        }
        psum[tid] = acc0 + acc1;
        __syncthreads();
        if (tid < 128)
            g_upart[u * C + tid] = psum[tid] + psum[tid + 128] + __ldg(bmlp + tid);
        return;
    }

    // ---- Z block ----
    __half* As = (__half*)sm;                    // 64 x 128 (lda 136)
    __half* Bs = (__half*)(sm + 64 * 136 * 2);
    float*  Cs = (float*)sm;                     // epilogue staging
    const int j0 = blockIdx.x * 64;
    const int wm = wid >> 2, wn = wid & 3;

    const float4 wv = __ldg((const float4*)(wdense + C) + lane);
    const float bias = __ldg(bd);

    // batched loads (MLP=8), then convert + store + dot
    float4 v[8];
    #pragma unroll
    for (int r = 0; r < 8; r++)
        v[r] = *(const float4*)(inter + ((size_t)(u * J + j0 + wid + 8 * r)) * C + lane * 4);
    #pragma unroll
    for (int r = 0; r < 8; r++) {
        int row = wid + 8 * r;
        __half2 h01 = __floats2half2_rn(v[r].x, v[r].y);
        __half2 h23 = __floats2half2_rn(v[r].z, v[r].w);
        uint2 pk; pk.x = *(unsigned*)&h01; pk.y = *(unsigned*)&h23;
        *(uint2*)(As + row * 136 + lane * 4) = pk;
        float d = v[r].x * wv.x + v[r].y * wv.y + v[r].z * wv.z + v[r].w * wv.w;
        #pragma unroll
        for (int off = 16; off; off >>= 1) d += __shfl_xor_sync(0xffffffffu, d, off);
        if (lane == 0) g_skb[u * J + j0 + row] = d + bias;
    }
    __syncthreads();

    wmma::fragment<wmma::accumulator, 16, 16, 16, float> acc[2][2];
    #pragma unroll
    for (int fi = 0; fi < 2; fi++)
        for (int fj = 0; fj < 2; fj++) wmma::fill_fragment(acc[fi][fj], 0.f);

    for (int k0 = 0; k0 < C; k0 += 64) {
        // Bs <- W_mlp[E+k0 .. E+k0+63, :] fp32->fp16 (L2-hot)
        #pragma unroll
        for (int r = 0; r < 8; r++) {
            int idx = tid + 256 * r;
            int br = idx >> 5, bc = (idx & 31) * 4;
            float4 t = __ldg((const float4*)(Wmlp + (size_t)(E + k0 + br) * C + bc));
            __half2 h01 = __floats2half2_rn(t.x, t.y);
            __half2 h23 = __floats2half2_rn(t.z, t.w);
            uint2 pk; pk.x = *(unsigned*)&h01; pk.y = *(unsigned*)&h23;
            *(uint2*)(Bs + br * 136 + bc) = pk;
        }
        __syncthreads();
        mma_tile64<136, 136>(As + k0, Bs, wm, wn, acc);
        __syncthreads();
    }

    // epilogue: acc -> Cs (union) -> fp16 Zh
    #pragma unroll
    for (int fi = 0; fi < 2; fi++)
        for (int fj = 0; fj < 2; fj++)
            wmma::store_matrix_sync(
                Cs + (wm * 32 + fi * 16) * 128 + wn * 32 + fj * 16,
                acc[fi][fj], 128, wmma::mem_row_major);
    __syncthreads();
    #pragma unroll
    for (int it = 0; it < 8; it++) {
        int idx = tid + 256 * it, row = idx >> 5, c4 = (idx & 31) * 4;
        float4 t = *(const float4*)(Cs + row * 128 + c4);
        __half2 h01 = __floats2half2_rn(t.x, t.y);
        __half2 h23 = __floats2half2_rn(t.z, t.w);
        uint2 pk; pk.x = *(unsigned*)&h01; pk.y = *(unsigned*)&h23;
        *(uint2*)(g_Zh + ((size_t)(u * J + j0 + row)) * C + c4) = pk;
    }
}

// ---------------- gemm_main: fused attention + pooling + MLP ----------------
// grid (I/128, U), 512 thr (16 warps), 173 KB dynamic smem, BM=128.
// Phase 0: st/skb/mask -> smem (all precomputed; trivial fills).
// Phase 1: w = exp(tanh(st+skb))*mask -> wsm fp16 (128x512); rowsum -> inv.
// Phase 2 (split): warps 0-7 MMA over J with cp.async double-buffered Bs;
//                  warps 8-15 stream normalized attn (256 KB) concurrently.
// Epilogue: relu(acc*inv + upart) -> out_ctx (Cs unioned over wsm).
constexpr int BM   = 128;
constexpr int LDW  = 520;                         // wsm half stride (bank-free)
constexpr int BOFF = BM * LDW * 2;                // 133,120
constexpr int BS_STAGE = 64 * 136;                // halves per stage
constexpr int SOFF = BOFF + 2 * BS_STAGE * 2;     // 167,936
constexpr int SMEM_MAIN = SOFF + (128 + 128 + 512 + 512) * 4;  // 173,056

__global__ __launch_bounds__(512, 1) void gemm_main_kernel(
    const void* __restrict__ mask,
    float* __restrict__ out_ctx, float* __restrict__ out_attn)
{
    extern __shared__ __align__(16) char dsm[];
    __half* wsm   = (__half*)dsm;            // 128 x 512 (ld 520)
    __half* Bs    = (__half*)(dsm + BOFF);   // [2][64*136]
    float*  Cs    = (float*)dsm;             // union over wsm, epilogue only
    float* st_sm  = (float*)(dsm + SOFF);
    float* inv_sm = st_sm + 128;
    float* skb_sm = inv_sm + 128;
    float* m_sm   = skb_sm + 512;

    const int u = blockIdx.y, m0 = blockIdx.x * BM;
    const int tid = threadIdx.x, wid = tid >> 5, lane = tid & 31;
    const float L2E = 1.4426950408889634f;

    // mask mode from partial flags (2 loads + warp-OR per thread)
    int fa = g_pa[lane], fb = g_pb[lane];
    fa = __reduce_or_sync(0xffffffffu, fa);
    fb = __reduce_or_sync(0xffffffffu, fb);
    const int mode = !fa ? 1 : (!fb ? 2 : 0);

    // phase 0: skb + mask + st -> smem (all precomputed in fusedz)
    {
        int k = tid;
        skb_sm[k] = g_skb[u * J + k];
        float mv;
        if (mode == 1)      mv = ((const int*)mask)[u * J + k] ? 1.f : 0.f;
        else if (mode == 2) mv = ((const float*)mask)[u * J + k];
        else                mv = ((const unsigned char*)mask)[u * J + k] ? 1.f : 0.f;
        m_sm[k] = mv;
        if (tid < 128) st_sm[tid] = g_st[u * I + m0 + tid];
    }
    __syncthreads();

    // phase 1: 4 threads per row, interleaved half2 cols (bank-conflict-free)
    {
        int row = tid >> 2, sub = tid & 3;
        float stv = st_sm[row];
        float sum = 0.f;
        #pragma unroll
        for (int k = 0; k < 64; k++) {
            int c = sub * 2 + 8 * k;
            float x0 = stv + skb_sm[c], x1 = stv + skb_sm[c + 1];
            float t0, t1, e0, e1;
            asm("tanh.approx.f32 %0,%1;" : "=f"(t0) : "f"(x0));
            asm("tanh.approx.f32 %0,%1;" : "=f"(t1) : "f"(x1));
            asm("ex2.approx.f32 %0,%1;"  : "=f"(e0) : "f"(t0 * L2E));
            asm("ex2.approx.f32 %0,%1;"  : "=f"(e1) : "f"(t1 * L2E));
            e0 *= m_sm[c]; e1 *= m_sm[c + 1];
            *(__half2*)(wsm + row * LDW + c) = __floats2half2_rn(e0, e1);
            sum += e0 + e1;
        }
        sum += __shfl_xor_sync(0xffffffffu, sum, 1);
        sum += __shfl_xor_sync(0xffffffffu, sum, 2);
        if (sub == 0) inv_sm[row] = __fdividef(1.f, sum);
    }
    __syncthreads();

    wmma::fragment<wmma::accumulator, 16, 16, 16, float> acc[4][2];

    if (tid < 256) {
        // ---- MMA warps: k-loop, double-buffered cp.async Bs ----
        const int wm = wid >> 2, wn = wid & 3;
        #pragma unroll
        for (int fi = 0; fi < 4; fi++)
            for (int fj = 0; fj < 2; fj++) wmma::fill_fragment(acc[fi][fj], 0.f);

        #pragma unroll
        for (int r = 0; r < 4; r++) {
            int idx = tid + 256 * r, br = idx >> 4, bc = (idx & 15) * 8;
            cp_async16(Bs + br * 136 + bc, g_Zh + ((size_t)u * J + br) * C + bc);
        }
        cp_commit();

        for (int kt = 0; kt < 8; kt++) {
            if (kt < 7) {
                __half* dst = Bs + ((kt + 1) & 1) * BS_STAGE;
                #pragma unroll
                for (int r = 0; r < 4; r++) {
                    int idx = tid + 256 * r, br = idx >> 4, bc = (idx & 15) * 8;
                    cp_async16(dst + br * 136 + bc,
                               g_Zh + ((size_t)u * J + (kt + 1) * 64 + br) * C + bc);
                }
                cp_commit();
                cp_wait<1>();
            } else {
                cp_wait<0>();
            }
            asm volatile("bar.sync 1, 256;" ::: "memory");
            mma_tile128<LDW, 136>(wsm + kt * 64, Bs + (kt & 1) * BS_STAGE, wm, wn, acc);
            asm volatile("bar.sync 1, 256;" ::: "memory");
        }
    } else {
        // ---- store warps: normalized attn -> gmem (overlaps MMA) ----
        int t = tid - 256;
        float* ab = out_attn + ((size_t)(u * I + m0)) * J;
        #pragma unroll
        for (int it = 0; it < 64; it++) {
            int idx = t + 256 * it;             // 16384 float4s
            int row = idx >> 7, c4 = (idx & 127) * 4;
            uint2 pk = *(uint2*)(wsm + row * LDW + c4);
            __half2 h01 = *(__half2*)&pk.x, h23 = *(__half2*)&pk.y;
            float iv = inv_sm[row];
            float2 f01 = __half22float2(h01), f23 = __half22float2(h23);
            *(float4*)(ab + row * J + c4) =
                make_float4(f01.x * iv, f01.y * iv, f23.x * iv, f23.y * iv);
        }
    }
    __syncthreads();   // store warps done reading wsm; Cs may now alias it

    if (tid < 256) {
        const int wm = wid >> 2, wn = wid & 3;
        #pragma unroll
        for (int fi = 0; fi < 4; fi++)
            for (int fj = 0; fj < 2; fj++)
                wmma::store_matrix_sync(
                    Cs + (wm * 64 + fi * 16) * 128 + wn * 32 + fj * 16,
                    acc[fi][fj], 128, wmma::mem_row_major);
    }
    __syncthreads();

    {
        const float4* up4 = (const float4*)(g_upart + u * C);
        float* ob = out_ctx + ((size_t)(u * I + m0)) * C;
        #pragma unroll
        for (int it = 0; it < 8; it++) {
            int idx = tid + 512 * it, row = idx >> 5, c4 = idx & 31;
            float4 v = ((const float4*)Cs)[idx];
            float iv = inv_sm[row];
            float4 up = __ldg(up4 + c4);
            v.x = fmaxf(fmaf(v.x, iv, up.x), 0.f);
            v.y = fmaxf(fmaf(v.y, iv, up.y), 0.f);
            v.z = fmaxf(fmaf(v.z, iv, up.z), 0.f);
            v.w = fmaxf(fmaf(v.w, iv, up.w), 0.f);
            ((float4*)ob)[idx] = v;
        }
    }
}

// ---------------- launcher ---------------------------------------------------
extern "C" void kernel_launch(void* const* d_in, const int* in_sizes, int n_in,
                              void* d_out, int out_size)
{
    const float* target = (const float*)d_in[0];  // (U,I,C)
    const float* inter  = (const float*)d_in[1];  // (U,J,C)
    const float* user   = (const float*)d_in[2];  // (U,E)
    const void*  mask   = d_in[3];                // (U,J) dtype sniffed
    const float* wdense = (const float*)d_in[4];  // (2C,)
    const float* bdense = (const float*)d_in[5];  // (1,)
    const float* Wmlp   = (const float*)d_in[6];  // (E+C, C)
    const float* bmlp   = (const float*)d_in[7];  // (C,)

    float* out_ctx  = (float*)d_out;                       // (U,I,C)
    float* out_attn = (float*)d_out + (size_t)U * I * C;   // (U,I,J)

    cudaFuncSetAttribute(gemm_main_kernel,
                         cudaFuncAttributeMaxDynamicSharedMemorySize, SMEM_MAIN);

    fusedz_kernel<<<dim3(14, U), 256>>>(inter, wdense, bdense,
                                        user, Wmlp, bmlp, target,
                                        (const unsigned*)mask);
    gemm_main_kernel<<<dim3(I / BM, U), 512, SMEM_MAIN>>>(mask, out_ctx, out_attn);
}

// round 11
// speedup vs baseline: 1.3442x; 1.0601x over previous
#include <cuda_runtime.h>
#include <cuda_fp16.h>
#include <mma.h>
#include <cstdint>

using namespace nvcuda;

// Problem dims (fixed by setup_inputs)
constexpr int U = 128, I = 256, J = 512, C = 128, E = 128;

// ---------------- scratch (device globals) ----------------------------------
__device__ float  g_skb[U * J];            // inter . w2 + b
__device__ float  g_st[U * I];             // target . w1
__device__ float  g_upart[U * C];          // user @ W1 + b_mlp
__device__ int    g_pa[32], g_pb[32];      // mask-sniff partial flags
__device__ __half g_Zh[U * J * C];         // Z = interacted @ W2, fp16

// ---------------- cp.async helpers ------------------------------------------
__device__ __forceinline__ void cp_async16(void* smem, const void* gmem)
{
    unsigned s = (unsigned)__cvta_generic_to_shared(smem);
    asm volatile("cp.async.cg.shared.global [%0], [%1], 16;" :: "r"(s), "l"(gmem));
}
__device__ __forceinline__ void cp_commit()
{
    asm volatile("cp.async.commit_group;" ::: "memory");
}
template<int N>
__device__ __forceinline__ void cp_wait()
{
    asm volatile("cp.async.wait_group %0;" :: "n"(N) : "memory");
}

// ---------------- MMA micro-tiles -------------------------------------------
template<int LDA, int LDB>
__device__ __forceinline__ void mma_tile64(
    const __half* A, const __half* B, int wm, int wn,
    wmma::fragment<wmma::accumulator, 16, 16, 16, float> (&acc)[2][2])
{
    #pragma unroll
    for (int kk = 0; kk < 64; kk += 16) {
        wmma::fragment<wmma::matrix_a, 16, 16, 16, __half, wmma::row_major> a[2];
        wmma::fragment<wmma::matrix_b, 16, 16, 16, __half, wmma::row_major> b[2];
        wmma::load_matrix_sync(a[0], A + (wm * 32) * LDA + kk, LDA);
        wmma::load_matrix_sync(a[1], A + (wm * 32 + 16) * LDA + kk, LDA);
        wmma::load_matrix_sync(b[0], B + kk * LDB + wn * 32, LDB);
        wmma::load_matrix_sync(b[1], B + kk * LDB + wn * 32 + 16, LDB);
        #pragma unroll
        for (int fi = 0; fi < 2; fi++)
            #pragma unroll
            for (int fj = 0; fj < 2; fj++)
                wmma::mma_sync(acc[fi][fj], a[fi], b[fj], acc[fi][fj]);
    }
}

// BM=128 warp tile (acc[4][2]), depth 128 per call
template<int LDA, int LDB>
__device__ __forceinline__ void mma_tile128_d128(
    const __half* A, const __half* B, int wm, int wn,
    wmma::fragment<wmma::accumulator, 16, 16, 16, float> (&acc)[4][2])
{
    #pragma unroll
    for (int kk = 0; kk < 128; kk += 16) {
        wmma::fragment<wmma::matrix_a, 16, 16, 16, __half, wmma::row_major> a[4];
        wmma::fragment<wmma::matrix_b, 16, 16, 16, __half, wmma::row_major> b[2];
        #pragma unroll
        for (int fi = 0; fi < 4; fi++)
            wmma::load_matrix_sync(a[fi], A + (wm * 64 + fi * 16) * LDA + kk, LDA);
        #pragma unroll
        for (int fj = 0; fj < 2; fj++)
            wmma::load_matrix_sync(b[fj], B + kk * LDB + wn * 32 + fj * 16, LDB);
        #pragma unroll
        for (int fi = 0; fi < 4; fi++)
            #pragma unroll
            for (int fj = 0; fj < 2; fj++)
                wmma::mma_sync(acc[fi][fj], a[fi], b[fj], acc[fi][fj]);
    }
}

// ---------------- fusedZ: inter -> skb + Zh; st folded in; upart, sniff ----
// grid (10, U), 256 thr.
//   x<8          : Z block (64 j-rows) + 32 st rows (m0 = x*32)
//   x==8         : upart for u
//   x==9 && u<32 : mask sniff partial
__global__ __launch_bounds__(256, 2) void fusedz_kernel(
    const float* __restrict__ inter, const float* __restrict__ wdense,
    const float* __restrict__ bd, const float* __restrict__ user,
    const float* __restrict__ Wmlp, const float* __restrict__ bmlp,
    const float* __restrict__ target, const unsigned* __restrict__ mask)
{
    __shared__ __align__(16) char sm[64 * 136 * 2 * 2];  // 34,816 B
    const int u = blockIdx.y;
    const int tid = threadIdx.x, wid = tid >> 5, lane = tid & 31;

    if (blockIdx.x == 9) {
        // ---- mask sniff partial ----
        if (u >= 32) return;
        int a = 0, b = 0;
        #pragma unroll
        for (int r = 0; r < 2; r++) {
            unsigned w = mask[u * 512 + tid + 256 * r];
            a |= (w != 0u && w != 1u);
            b |= (w != 0u && w != 0x3F800000u);
        }
        int* s_f = (int*)sm;
        if (tid == 0) { s_f[0] = 0; s_f[1] = 0; }
        __syncthreads();
        a = __reduce_or_sync(0xffffffffu, a);
        b = __reduce_or_sync(0xffffffffu, b);
        if (lane == 0) { atomicOr(&s_f[0], a); atomicOr(&s_f[1], b); }
        __syncthreads();
        if (tid == 0) { g_pa[u] = s_f[0]; g_pb[u] = s_f[1]; }
        return;
    }

    if (blockIdx.x == 8) {
        // ---- upart: g_upart[u] = user[u] @ Wmlp[:E] + bmlp ----
        float* usm  = (float*)sm;          // 128 floats
        float* psum = usm + 128;           // 256 floats
        if (tid < 128) usm[tid] = user[u * E + tid];
        __syncthreads();
        int c = tid & 127, h = tid >> 7;
        float acc0 = 0.f, acc1 = 0.f;
        int e0 = h * 64;
        #pragma unroll 16
        for (int e = 0; e < 64; e += 2) {
            acc0 += usm[e0 + e]     * __ldg(Wmlp + (e0 + e) * C + c);
            acc1 += usm[e0 + e + 1] * __ldg(Wmlp + (e0 + e + 1) * C + c);
        }
        psum[tid] = acc0 + acc1;
        __syncthreads();
        if (tid < 128)
            g_upart[u * C + tid] = psum[tid] + psum[tid + 128] + __ldg(bmlp + tid);
        return;
    }

    // ---- Z block (+ st rows) ----
    __half* As = (__half*)sm;                    // 64 x 128 (lda 136)
    __half* Bs = (__half*)(sm + 64 * 136 * 2);
    float*  Cs = (float*)sm;                     // epilogue staging
    const int j0 = blockIdx.x * 64;
    const int m0 = blockIdx.x * 32;              // st rows for this block
    const int wm = wid >> 2, wn = wid & 3;

    const float4 wv1 = __ldg((const float4*)wdense + lane);
    const float4 wv2 = __ldg((const float4*)(wdense + C) + lane);
    const float bias = __ldg(bd);

    // batched loads: 8 inter rows + 4 target rows per warp (12 outstanding)
    float4 v[8], tv[4];
    #pragma unroll
    for (int r = 0; r < 8; r++)
        v[r] = *(const float4*)(inter + ((size_t)(u * J + j0 + wid + 8 * r)) * C + lane * 4);
    #pragma unroll
    for (int r = 0; r < 4; r++)
        tv[r] = *(const float4*)(target + ((size_t)(u * I + m0 + wid * 4 + r)) * C + lane * 4);

    #pragma unroll
    for (int r = 0; r < 8; r++) {
        int row = wid + 8 * r;
        __half2 h01 = __floats2half2_rn(v[r].x, v[r].y);
        __half2 h23 = __floats2half2_rn(v[r].z, v[r].w);
        uint2 pk; pk.x = *(unsigned*)&h01; pk.y = *(unsigned*)&h23;
        *(uint2*)(As + row * 136 + lane * 4) = pk;
        float d = v[r].x * wv2.x + v[r].y * wv2.y + v[r].z * wv2.z + v[r].w * wv2.w;
        #pragma unroll
        for (int off = 16; off; off >>= 1) d += __shfl_xor_sync(0xffffffffu, d, off);
        if (lane == 0) g_skb[u * J + j0 + row] = d + bias;
    }
    #pragma unroll
    for (int r = 0; r < 4; r++) {
        float d = tv[r].x * wv1.x + tv[r].y * wv1.y + tv[r].z * wv1.z + tv[r].w * wv1.w;
        #pragma unroll
        for (int off = 16; off; off >>= 1) d += __shfl_xor_sync(0xffffffffu, d, off);
        if (lane == 0) g_st[u * I + m0 + wid * 4 + r] = d;
    }
    __syncthreads();

    wmma::fragment<wmma::accumulator, 16, 16, 16, float> acc[2][2];
    #pragma unroll
    for (int fi = 0; fi < 2; fi++)
        for (int fj = 0; fj < 2; fj++) wmma::fill_fragment(acc[fi][fj], 0.f);

    for (int k0 = 0; k0 < C; k0 += 64) {
        // Bs <- W_mlp[E+k0 .. E+k0+63, :] fp32->fp16 (L2-hot)
        #pragma unroll
        for (int r = 0; r < 8; r++) {
            int idx = tid + 256 * r;
            int br = idx >> 5, bc = (idx & 31) * 4;
            float4 t = __ldg((const float4*)(Wmlp + (size_t)(E + k0 + br) * C + bc));
            __half2 h01 = __floats2half2_rn(t.x, t.y);
            __half2 h23 = __floats2half2_rn(t.z, t.w);
            uint2 pk; pk.x = *(unsigned*)&h01; pk.y = *(unsigned*)&h23;
            *(uint2*)(Bs + br * 136 + bc) = pk;
        }
        __syncthreads();
        mma_tile64<136, 136>(As + k0, Bs, wm, wn, acc);
        __syncthreads();
    }

    // epilogue: acc -> Cs (union) -> fp16 Zh
    #pragma unroll
    for (int fi = 0; fi < 2; fi++)
        for (int fj = 0; fj < 2; fj++)
            wmma::store_matrix_sync(
                Cs + (wm * 32 + fi * 16) * 128 + wn * 32 + fj * 16,
                acc[fi][fj], 128, wmma::mem_row_major);
    __syncthreads();
    #pragma unroll
    for (int it = 0; it < 8; it++) {
        int idx = tid + 256 * it, row = idx >> 5, c4 = (idx & 31) * 4;
        float4 t = *(const float4*)(Cs + row * 128 + c4);
        __half2 h01 = __floats2half2_rn(t.x, t.y);
        __half2 h23 = __floats2half2_rn(t.z, t.w);
        uint2 pk; pk.x = *(unsigned*)&h01; pk.y = *(unsigned*)&h23;
        *(uint2*)(g_Zh + ((size_t)(u * J + j0 + row)) * C + c4) = pk;
    }
}

// ---------------- gemm_main: fused attention + pooling + MLP ----------------
// grid (I/128, U), 512 thr, ~208 KB smem, BM=128, BK=128 (4 k-iters).
// Stage-0 Bs prefetched (all threads) BEFORE the MUFU phase.
constexpr int BM   = 128;
constexpr int BK   = 128;
constexpr int LDW  = 520;                          // wsm half stride
constexpr int BOFF = BM * LDW * 2;                 // 133,120
constexpr int BS_STAGE = BK * 136;                 // halves per stage
constexpr int SOFF = BOFF + 2 * BS_STAGE * 2;      // 202,752
constexpr int SMEM_MAIN = SOFF + (128 + 128 + 512 + 512) * 4;  // 207,872

__global__ __launch_bounds__(512, 1) void gemm_main_kernel(
    const void* __restrict__ mask,
    float* __restrict__ out_ctx, float* __restrict__ out_attn)
{
    extern __shared__ __align__(16) char dsm[];
    __half* wsm   = (__half*)dsm;            // 128 x 512 (ld 520)
    __half* Bs    = (__half*)(dsm + BOFF);   // [2][128*136]
    float*  Cs    = (float*)dsm;             // union over wsm, epilogue only
    float* st_sm  = (float*)(dsm + SOFF);
    float* inv_sm = st_sm + 128;
    float* skb_sm = inv_sm + 128;
    float* m_sm   = skb_sm + 512;

    const int u = blockIdx.y, m0 = blockIdx.x * BM;
    const int tid = threadIdx.x, wid = tid >> 5, lane = tid & 31;
    const float L2E = 1.4426950408889634f;

    // mask mode from partial flags
    int fa = g_pa[lane], fb = g_pb[lane];
    fa = __reduce_or_sync(0xffffffffu, fa);
    fb = __reduce_or_sync(0xffffffffu, fb);
    const int mode = !fa ? 1 : (!fb ? 2 : 0);

    // prefetch Bs stage 0 (all 512 threads, 4 x cp.async16 each)
    #pragma unroll
    for (int r = 0; r < 4; r++) {
        int idx = tid + 512 * r;                 // 2048 chunks
        int br = idx >> 4, bc = (idx & 15) * 8;
        cp_async16(Bs + br * 136 + bc, g_Zh + ((size_t)u * J + br) * C + bc);
    }
    cp_commit();

    // phase 0: skb + mask + st -> smem (all precomputed in fusedz)
    {
        int k = tid;
        skb_sm[k] = g_skb[u * J + k];
        float mv;
        if (mode == 1)      mv = ((const int*)mask)[u * J + k] ? 1.f : 0.f;
        else if (mode == 2) mv = ((const float*)mask)[u * J + k];
        else                mv = ((const unsigned char*)mask)[u * J + k] ? 1.f : 0.f;
        m_sm[k] = mv;
        if (tid < 128) st_sm[tid] = g_st[u * I + m0 + tid];
    }
    __syncthreads();

    // phase 1: 4 threads per row, interleaved half2 cols (bank-conflict-free)
    {
        int row = tid >> 2, sub = tid & 3;
        float stv = st_sm[row];
        float sum = 0.f;
        #pragma unroll
        for (int k = 0; k < 64; k++) {
            int c = sub * 2 + 8 * k;
            float x0 = stv + skb_sm[c], x1 = stv + skb_sm[c + 1];
            float t0, t1, e0, e1;
            asm("tanh.approx.f32 %0,%1;" : "=f"(t0) : "f"(x0));
            asm("tanh.approx.f32 %0,%1;" : "=f"(t1) : "f"(x1));
            asm("ex2.approx.f32 %0,%1;"  : "=f"(e0) : "f"(t0 * L2E));
            asm("ex2.approx.f32 %0,%1;"  : "=f"(e1) : "f"(t1 * L2E));
            e0 *= m_sm[c]; e1 *= m_sm[c + 1];
            *(__half2*)(wsm + row * LDW + c) = __floats2half2_rn(e0, e1);
            sum += e0 + e1;
        }
        sum += __shfl_xor_sync(0xffffffffu, sum, 1);
        sum += __shfl_xor_sync(0xffffffffu, sum, 2);
        if (sub == 0) inv_sm[row] = __fdividef(1.f, sum);
    }
    cp_wait<0>();       // stage 0 landed (own copies); barrier publishes all
    __syncthreads();

    wmma::fragment<wmma::accumulator, 16, 16, 16, float> acc[4][2];

    if (tid < 256) {
        // ---- MMA warps: 4 k-iters of depth 128, double-buffered Bs ----
        const int wm = wid >> 2, wn = wid & 3;
        #pragma unroll
        for (int fi = 0; fi < 4; fi++)
            for (int fj = 0; fj < 2; fj++) wmma::fill_fragment(acc[fi][fj], 0.f);

        for (int kt = 0; kt < 4; kt++) {
            if (kt < 3) {
                __half* dst = Bs + ((kt + 1) & 1) * BS_STAGE;
                #pragma unroll
                for (int r = 0; r < 8; r++) {
                    int idx = tid + 256 * r;     // 2048 chunks
                    int br = idx >> 4, bc = (idx & 15) * 8;
                    cp_async16(dst + br * 136 + bc,
                               g_Zh + ((size_t)u * J + (kt + 1) * BK + br) * C + bc);
                }
                cp_commit();
                cp_wait<1>();
            } else {
                cp_wait<0>();
            }
            asm volatile("bar.sync 1, 256;" ::: "memory");
            mma_tile128_d128<LDW, 136>(wsm + kt * BK, Bs + (kt & 1) * BS_STAGE,
                                       wm, wn, acc);
            asm volatile("bar.sync 1, 256;" ::: "memory");
        }
    } else {
        // ---- store warps: normalized attn -> gmem (overlaps MMA) ----
        int t = tid - 256;
        float* ab = out_attn + ((size_t)(u * I + m0)) * J;
        #pragma unroll
        for (int it = 0; it < 64; it++) {
            int idx = t + 256 * it;              // 16384 float4s
            int row = idx >> 7, c4 = (idx & 127) * 4;
            uint2 pk = *(uint2*)(wsm + row * LDW + c4);
            __half2 h01 = *(__half2*)&pk.x, h23 = *(__half2*)&pk.y;
            float iv = inv_sm[row];
            float2 f01 = __half22float2(h01), f23 = __half22float2(h23);
            *(float4*)(ab + row * J + c4) =
                make_float4(f01.x * iv, f01.y * iv, f23.x * iv, f23.y * iv);
        }
    }
    __syncthreads();   // store warps done reading wsm; Cs may now alias it

    if (tid < 256) {
        const int wm = wid >> 2, wn = wid & 3;
        #pragma unroll
        for (int fi = 0; fi < 4; fi++)
            for (int fj = 0; fj < 2; fj++)
                wmma::store_matrix_sync(
                    Cs + (wm * 64 + fi * 16) * 128 + wn * 32 + fj * 16,
                    acc[fi][fj], 128, wmma::mem_row_major);
    }
    __syncthreads();

    {
        const float4* up4 = (const float4*)(g_upart + u * C);
        float* ob = out_ctx + ((size_t)(u * I + m0)) * C;
        #pragma unroll
        for (int it = 0; it < 8; it++) {
            int idx = tid + 512 * it, row = idx >> 5, c4 = idx & 31;
            float4 v = ((const float4*)Cs)[idx];
            float iv = inv_sm[row];
            float4 up = __ldg(up4 + c4);
            v.x = fmaxf(fmaf(v.x, iv, up.x), 0.f);
            v.y = fmaxf(fmaf(v.y, iv, up.y), 0.f);
            v.z = fmaxf(fmaf(v.z, iv, up.z), 0.f);
            v.w = fmaxf(fmaf(v.w, iv, up.w), 0.f);
            ((float4*)ob)[idx] = v;
        }
    }
}

// ---------------- launcher ---------------------------------------------------
extern "C" void kernel_launch(void* const* d_in, const int* in_sizes, int n_in,
                              void* d_out, int out_size)
{
    const float* target = (const float*)d_in[0];  // (U,I,C)
    const float* inter  = (const float*)d_in[1];  // (U,J,C)
    const float* user   = (const float*)d_in[2];  // (U,E)
    const void*  mask   = d_in[3];                // (U,J) dtype sniffed
    const float* wdense = (const float*)d_in[4];  // (2C,)
    const float* bdense = (const float*)d_in[5];  // (1,)
    const float* Wmlp   = (const float*)d_in[6];  // (E+C, C)
    const float* bmlp   = (const float*)d_in[7];  // (C,)

    float* out_ctx  = (float*)d_out;                       // (U,I,C)
    float* out_attn = (float*)d_out + (size_t)U * I * C;   // (U,I,J)

    cudaFuncSetAttribute(gemm_main_kernel,
                         cudaFuncAttributeMaxDynamicSharedMemorySize, SMEM_MAIN);

    fusedz_kernel<<<dim3(10, U), 256>>>(inter, wdense, bdense,
                                        user, Wmlp, bmlp, target,
                                        (const unsigned*)mask);
    gemm_main_kernel<<<dim3(I / BM, U), 512, SMEM_MAIN>>>(mask, out_ctx, out_attn);
}